// round 14
// baseline (speedup 1.0000x reference)
#include <cuda_runtime.h>
#include <cstdint>

#define NN 50000
#define EE 800000
#define SCAN_BLOCKS ((NN + 1023) / 1024)   // 49

// ---------------- scratch (device globals, referenced directly) -------------
__device__ float g_y[NN * 128];      // A @ Wl  (per layer)
__device__ float g_z[NN * 128];      // A @ Wr + b
__device__ float g_h[NN * 128];      // layer activation
__device__ int   g_rowptr[NN + 1];   // CSR row pointers (by dst)
__device__ int   g_cnt[NN];          // in-degree histogram
__device__ int   g_cursor[NN];       // fill cursors
__device__ int   g_eidx[EE];         // src node id per CSR slot
__device__ int   g_is64;             // edge_index dtype flag
__device__ int   g_bsum[SCAN_BLOCKS];
__device__ int   g_boff[SCAN_BLOCKS];

// ---------------- edge_index dtype detection --------------------------------
__global__ void detect_dtype(const void* __restrict__ ei) {
    if (threadIdx.x != 0 || blockIdx.x != 0) return;
    const long long* p = (const long long*)ei;
    int ok64 = 1;
    for (int i = 0; i < 64; i++) {
        long long v = p[i];
        if (v < 0 || v >= NN) { ok64 = 0; break; }
    }
    g_is64 = ok64;
}

__device__ __forceinline__ int load_idx(const void* __restrict__ ei, int which, int e) {
    if (g_is64) {
        const long long* p = (const long long*)ei;
        return (int)p[(size_t)which * EE + e];
    } else {
        const int* p = (const int*)ei;
        return p[(size_t)which * EE + e];
    }
}

// ---------------- CSR build ----------------
__global__ void csr_clear() {
    int i = blockIdx.x * blockDim.x + threadIdx.x;
    if (i < NN) { g_cnt[i] = 0; g_cursor[i] = 0; }
}

__global__ void csr_hist(const void* __restrict__ ei) {
    int e = blockIdx.x * blockDim.x + threadIdx.x;
    if (e < EE) atomicAdd(&g_cnt[load_idx(ei, 1, e)], 1);
}

__global__ void __launch_bounds__(1024) csr_scan1() {
    int i = blockIdx.x * 1024 + threadIdx.x;
    int v = (i < NN) ? g_cnt[i] : 0;
    int lane = threadIdx.x & 31, wid = threadIdx.x >> 5;
    int x = v;
#pragma unroll
    for (int off = 1; off < 32; off <<= 1) {
        int t = __shfl_up_sync(0xffffffffu, x, off);
        if (lane >= off) x += t;
    }
    __shared__ int wsum[32];
    if (lane == 31) wsum[wid] = x;
    __syncthreads();
    if (wid == 0) {
        int w = wsum[lane];
#pragma unroll
        for (int off = 1; off < 32; off <<= 1) {
            int t = __shfl_up_sync(0xffffffffu, w, off);
            if (lane >= off) w += t;
        }
        wsum[lane] = w;
    }
    __syncthreads();
    int base = wid ? wsum[wid - 1] : 0;
    if (i < NN) g_rowptr[i] = base + x - v;
    if (threadIdx.x == 0) g_bsum[blockIdx.x] = wsum[31];
}

__global__ void csr_scan2() {
    if (threadIdx.x == 0 && blockIdx.x == 0) {
        int run = 0;
        for (int b = 0; b < SCAN_BLOCKS; b++) { g_boff[b] = run; run += g_bsum[b]; }
        g_rowptr[NN] = run;
    }
}

__global__ void __launch_bounds__(1024) csr_scan3() {
    int i = blockIdx.x * 1024 + threadIdx.x;
    if (i < NN) g_rowptr[i] += g_boff[blockIdx.x];
}

__global__ void csr_fill(const void* __restrict__ ei) {
    int e = blockIdx.x * blockDim.x + threadIdx.x;
    if (e >= EE) return;
    int d = load_idx(ei, 1, e);
    int pos = atomicAdd(&g_cursor[d], 1);
    g_eidx[g_rowptr[d] + pos] = load_idx(ei, 0, e);
}

// ---------------- TF32 helpers ----------------
__device__ __forceinline__ uint32_t f2tf32(float x) {
    uint32_t r;
    asm("cvt.rna.tf32.f32 %0, %1;" : "=r"(r) : "f"(x));
    return r;
}
__device__ __forceinline__ void split_tf32(float v, float& hi, float& lo) {
    uint32_t h = f2tf32(v);
    hi = __uint_as_float(h);
    lo = __uint_as_float(f2tf32(v - __uint_as_float(h)));
}
__device__ __forceinline__ void mma8(float* d, const uint32_t* a, const uint32_t* b) {
    asm volatile(
        "mma.sync.aligned.m16n8k8.row.col.f32.tf32.tf32.f32 "
        "{%0,%1,%2,%3}, {%4,%5,%6,%7}, {%8,%9}, {%0,%1,%2,%3};"
        : "+f"(d[0]), "+f"(d[1]), "+f"(d[2]), "+f"(d[3])
        : "r"(a[0]), "r"(a[1]), "r"(a[2]), "r"(a[3]), "r"(b[0]), "r"(b[1]));
}

// ---------------- merged TF32 GEMM pair: g_y = A@Bl, g_z = A@Br (+bias) -----
// BM=128, BN=64, BK=16, 256 threads = 8 warps (4 m x 2 n), warp tile 32x32 x2.
// 3xTF32 with hi/lo planes PRE-SPLIT in smem during fill: inner loop is pure
// LDS + MMA (no cvt chains, no redundant per-warp splits).
template <int NC, int A_FROM_H>
__global__ void __launch_bounds__(256) sgemm_pair_tc(const float* __restrict__ Aparam,
                                                     const float* __restrict__ Bl,
                                                     const float* __restrict__ Br,
                                                     const float* __restrict__ bias,
                                                     int M) {
    const float* A = A_FROM_H ? g_h : Aparam;
    const int K = 128;

    __shared__ float Ahi[16][132], Alo[16][132];   // k-major [k][m]
    __shared__ float Bhl[16][68],  Bll[16][68];    // k-major [k][n]
    __shared__ float Bhr[16][68],  Blr[16][68];

    int tid = threadIdx.x;
    int wid = tid >> 5;
    int lane = tid & 31;
    int warp_m = wid & 3;            // 0..3 -> 32-row slice
    int warp_n = wid >> 2;           // 0..1 -> 32-col slice
    int r = lane >> 2;               // groupID 0..7
    int c = lane & 3;                // threadID_in_group 0..3

    int row0 = blockIdx.y * 128;
    int col0 = blockIdx.x * 64;

    float accl[2][4][4] = {};        // [mtile][ntile][frag]
    float accr[2][4][4] = {};

    for (int k0 = 0; k0 < K; k0 += 16) {
        // ---- fill A planes: 128 rows x 4 float4 (16 k-values), split once ----
#pragma unroll
        for (int i = 0; i < 2; i++) {
            int f = tid + i * 256;               // 0..511
            int ar = f >> 2, ac = f & 3;
            float4 v = make_float4(0.f, 0.f, 0.f, 0.f);
            if (row0 + ar < M)
                v = *(const float4*)(A + (size_t)(row0 + ar) * K + k0 + ac * 4);
            float h, l;
            split_tf32(v.x, h, l); Ahi[ac * 4 + 0][ar] = h; Alo[ac * 4 + 0][ar] = l;
            split_tf32(v.y, h, l); Ahi[ac * 4 + 1][ar] = h; Alo[ac * 4 + 1][ar] = l;
            split_tf32(v.z, h, l); Ahi[ac * 4 + 2][ar] = h; Alo[ac * 4 + 2][ar] = l;
            split_tf32(v.w, h, l); Ahi[ac * 4 + 3][ar] = h; Alo[ac * 4 + 3][ar] = l;
        }
        // ---- fill B planes: 16 rows x 16 float4 per matrix, split once ----
        {
            int f = tid;                          // 0..255
            int br = f >> 4, bc = f & 15;
            float4 wl = *(const float4*)(Bl + (size_t)(k0 + br) * NC + col0 + bc * 4);
            float4 wr = *(const float4*)(Br + (size_t)(k0 + br) * NC + col0 + bc * 4);
            float h, l;
            split_tf32(wl.x, h, l); Bhl[br][bc * 4 + 0] = h; Bll[br][bc * 4 + 0] = l;
            split_tf32(wl.y, h, l); Bhl[br][bc * 4 + 1] = h; Bll[br][bc * 4 + 1] = l;
            split_tf32(wl.z, h, l); Bhl[br][bc * 4 + 2] = h; Bll[br][bc * 4 + 2] = l;
            split_tf32(wl.w, h, l); Bhl[br][bc * 4 + 3] = h; Bll[br][bc * 4 + 3] = l;
            split_tf32(wr.x, h, l); Bhr[br][bc * 4 + 0] = h; Blr[br][bc * 4 + 0] = l;
            split_tf32(wr.y, h, l); Bhr[br][bc * 4 + 1] = h; Blr[br][bc * 4 + 1] = l;
            split_tf32(wr.z, h, l); Bhr[br][bc * 4 + 2] = h; Blr[br][bc * 4 + 2] = l;
            split_tf32(wr.w, h, l); Bhr[br][bc * 4 + 3] = h; Blr[br][bc * 4 + 3] = l;
        }
        __syncthreads();

#pragma unroll
        for (int kk = 0; kk < 16; kk += 8) {
            // A fragments (2 m-tiles), hi + lo
            uint32_t ahi[2][4], alo[2][4];
#pragma unroll
            for (int mt = 0; mt < 2; mt++) {
                int m0 = warp_m * 32 + mt * 16;
                ahi[mt][0] = __float_as_uint(Ahi[kk + c][m0 + r]);
                ahi[mt][1] = __float_as_uint(Ahi[kk + c][m0 + r + 8]);
                ahi[mt][2] = __float_as_uint(Ahi[kk + c + 4][m0 + r]);
                ahi[mt][3] = __float_as_uint(Ahi[kk + c + 4][m0 + r + 8]);
                alo[mt][0] = __float_as_uint(Alo[kk + c][m0 + r]);
                alo[mt][1] = __float_as_uint(Alo[kk + c][m0 + r + 8]);
                alo[mt][2] = __float_as_uint(Alo[kk + c + 4][m0 + r]);
                alo[mt][3] = __float_as_uint(Alo[kk + c + 4][m0 + r + 8]);
            }
            // B fragments (4 n-tiles per matrix), hi + lo
            uint32_t bhl[4][2], bll2[4][2], bhr[4][2], blr2[4][2];
#pragma unroll
            for (int nt = 0; nt < 4; nt++) {
                int n0 = warp_n * 32 + nt * 8 + r;
                bhl[nt][0]  = __float_as_uint(Bhl[kk + c][n0]);
                bhl[nt][1]  = __float_as_uint(Bhl[kk + c + 4][n0]);
                bll2[nt][0] = __float_as_uint(Bll[kk + c][n0]);
                bll2[nt][1] = __float_as_uint(Bll[kk + c + 4][n0]);
                bhr[nt][0]  = __float_as_uint(Bhr[kk + c][n0]);
                bhr[nt][1]  = __float_as_uint(Bhr[kk + c + 4][n0]);
                blr2[nt][0] = __float_as_uint(Blr[kk + c][n0]);
                blr2[nt][1] = __float_as_uint(Blr[kk + c + 4][n0]);
            }
            // 3xTF32 MMAs
#pragma unroll
            for (int mt = 0; mt < 2; mt++) {
#pragma unroll
                for (int nt = 0; nt < 4; nt++) {
                    mma8(accl[mt][nt], ahi[mt], bhl[nt]);
                    mma8(accl[mt][nt], ahi[mt], bll2[nt]);
                    mma8(accl[mt][nt], alo[mt], bhl[nt]);
                    mma8(accr[mt][nt], ahi[mt], bhr[nt]);
                    mma8(accr[mt][nt], ahi[mt], blr2[nt]);
                    mma8(accr[mt][nt], alo[mt], bhr[nt]);
                }
            }
        }
        __syncthreads();
    }

    // ---- epilogue ----
#pragma unroll
    for (int mt = 0; mt < 2; mt++) {
#pragma unroll
        for (int nt = 0; nt < 4; nt++) {
            int row = row0 + warp_m * 32 + mt * 16 + r;
            int col = col0 + warp_n * 32 + nt * 8 + 2 * c;
            float2 bb = *(const float2*)(bias + col);
            if (row < M) {
                *(float2*)(g_y + (size_t)row * NC + col) =
                    make_float2(accl[mt][nt][0], accl[mt][nt][1]);
                *(float2*)(g_z + (size_t)row * NC + col) =
                    make_float2(accr[mt][nt][0] + bb.x, accr[mt][nt][1] + bb.y);
            }
            if (row + 8 < M) {
                *(float2*)(g_y + (size_t)(row + 8) * NC + col) =
                    make_float2(accl[mt][nt][2], accl[mt][nt][3]);
                *(float2*)(g_z + (size_t)(row + 8) * NC + col) =
                    make_float2(accr[mt][nt][2] + bb.x, accr[mt][nt][3] + bb.y);
            }
        }
    }
}

// ---------------- fused gather + combine: warp per destination node ---------
template <bool RELU, bool TO_H>
__global__ void __launch_bounds__(256) gather128(float* __restrict__ outparam) {
    int w = (blockIdx.x * blockDim.x + threadIdx.x) >> 5;
    if (w >= NN) return;
    int lane = threadIdx.x & 31;
    int beg = g_rowptr[w], end = g_rowptr[w + 1];

    float4 acc = make_float4(0.f, 0.f, 0.f, 0.f);
    int j = beg;
    for (; j + 2 <= end; j += 2) {
        int s0 = g_eidx[j];
        int s1 = g_eidx[j + 1];
        float4 a = *(const float4*)(g_y + (size_t)s0 * 128 + lane * 4);
        float4 b = *(const float4*)(g_y + (size_t)s1 * 128 + lane * 4);
        acc.x += a.x + b.x; acc.y += a.y + b.y;
        acc.z += a.z + b.z; acc.w += a.w + b.w;
    }
    if (j < end) {
        int s0 = g_eidx[j];
        float4 a = *(const float4*)(g_y + (size_t)s0 * 128 + lane * 4);
        acc.x += a.x; acc.y += a.y; acc.z += a.z; acc.w += a.w;
    }

    float dv = 1.0f / fmaxf((float)(end - beg), 1.0f);
    float4 zz = *(const float4*)(g_z + (size_t)w * 128 + lane * 4);
    float4 o;
    o.x = acc.x * dv + zz.x;
    o.y = acc.y * dv + zz.y;
    o.z = acc.z * dv + zz.z;
    o.w = acc.w * dv + zz.w;
    if (RELU) {
        o.x = fmaxf(o.x, 0.f); o.y = fmaxf(o.y, 0.f);
        o.z = fmaxf(o.z, 0.f); o.w = fmaxf(o.w, 0.f);
    }
    float* out = TO_H ? g_h : outparam;
    *(float4*)(out + (size_t)w * 128 + lane * 4) = o;
}

template <bool RELU, bool TO_H>
__global__ void __launch_bounds__(256) gather64(float* __restrict__ outparam) {
    int w = (blockIdx.x * blockDim.x + threadIdx.x) >> 5;
    if (w >= NN) return;
    int lane = threadIdx.x & 31;
    int beg = g_rowptr[w], end = g_rowptr[w + 1];

    float2 acc = make_float2(0.f, 0.f);
    int j = beg;
    for (; j + 2 <= end; j += 2) {
        int s0 = g_eidx[j];
        int s1 = g_eidx[j + 1];
        float2 a = *(const float2*)(g_y + (size_t)s0 * 64 + lane * 2);
        float2 b = *(const float2*)(g_y + (size_t)s1 * 64 + lane * 2);
        acc.x += a.x + b.x; acc.y += a.y + b.y;
    }
    if (j < end) {
        int s0 = g_eidx[j];
        float2 a = *(const float2*)(g_y + (size_t)s0 * 64 + lane * 2);
        acc.x += a.x; acc.y += a.y;
    }

    float dv = 1.0f / fmaxf((float)(end - beg), 1.0f);
    float2 zz = *(const float2*)(g_z + (size_t)w * 64 + lane * 2);
    float2 o;
    o.x = acc.x * dv + zz.x;
    o.y = acc.y * dv + zz.y;
    if (RELU) { o.x = fmaxf(o.x, 0.f); o.y = fmaxf(o.y, 0.f); }
    float* out = TO_H ? g_h : outparam;
    *(float2*)(out + (size_t)w * 64 + lane * 2) = o;
}

// ---------------- launch ----------------
extern "C" void kernel_launch(void* const* d_in, const int* in_sizes, int n_in,
                              void* d_out, int out_size) {
    const float* x = (const float*)d_in[0];
    const void* ei = d_in[1];
    const float* Wl0 = (const float*)d_in[2];
    const float* b0  = (const float*)d_in[3];
    const float* Wr0 = (const float*)d_in[4];
    const float* Wl1 = (const float*)d_in[5];
    const float* b1  = (const float*)d_in[6];
    const float* Wr1 = (const float*)d_in[7];
    const float* Wl2 = (const float*)d_in[8];
    const float* b2  = (const float*)d_in[9];
    const float* Wr2 = (const float*)d_in[10];
    float* out = (float*)d_out;

    // ---- CSR build ----
    detect_dtype<<<1, 32>>>(ei);
    csr_clear<<<(NN + 255) / 256, 256>>>();
    csr_hist<<<(EE + 255) / 256, 256>>>(ei);
    csr_scan1<<<SCAN_BLOCKS, 1024>>>();
    csr_scan2<<<1, 32>>>();
    csr_scan3<<<SCAN_BLOCKS, 1024>>>();
    csr_fill<<<(EE + 255) / 256, 256>>>(ei);

    dim3 g128(2, (NN + 127) / 128);
    dim3 g64(1, (NN + 127) / 128);
    const int gather_blocks = (NN * 32 + 255) / 256;

    // ---- layer 0: input = x ----
    sgemm_pair_tc<128, 0><<<g128, 256>>>(x, Wl0, Wr0, b0, NN);
    gather128<true, true><<<gather_blocks, 256>>>(nullptr);

    // ---- layer 1: input = g_h ----
    sgemm_pair_tc<128, 1><<<g128, 256>>>(nullptr, Wl1, Wr1, b1, NN);
    gather128<true, true><<<gather_blocks, 256>>>(nullptr);

    // ---- layer 2: input = g_h, dout = 64 ----
    sgemm_pair_tc<64, 1><<<g64, 256>>>(nullptr, Wl2, Wr2, b2, NN);
    gather64<false, false><<<gather_blocks, 256>>>(out);
}

// round 15
// speedup vs baseline: 1.6322x; 1.6322x over previous
#include <cuda_runtime.h>
#include <cstdint>

#define NN 50000
#define EE 800000
#define SCAN_BLOCKS ((NN + 1023) / 1024)   // 49

// ---------------- scratch (device globals, referenced directly) -------------
__device__ float g_y[NN * 128];      // A @ Wl  (per layer)
__device__ float g_z[NN * 128];      // A @ Wr + b
__device__ float g_h[NN * 128];      // layer activation
__device__ int   g_rowptr[NN + 1];   // CSR row pointers (by dst)
__device__ int   g_cnt[NN];          // in-degree histogram
__device__ int   g_cursor[NN];       // fill cursors
__device__ int   g_eidx[EE];         // src node id per CSR slot
__device__ int   g_is64;             // edge_index dtype flag
__device__ int   g_bsum[SCAN_BLOCKS];
__device__ int   g_boff[SCAN_BLOCKS];

// ---------------- edge_index dtype detection --------------------------------
__global__ void detect_dtype(const void* __restrict__ ei) {
    if (threadIdx.x != 0 || blockIdx.x != 0) return;
    const long long* p = (const long long*)ei;
    int ok64 = 1;
    for (int i = 0; i < 64; i++) {
        long long v = p[i];
        if (v < 0 || v >= NN) { ok64 = 0; break; }
    }
    g_is64 = ok64;
}

__device__ __forceinline__ int load_idx(const void* __restrict__ ei, int which, int e) {
    if (g_is64) {
        const long long* p = (const long long*)ei;
        return (int)p[(size_t)which * EE + e];
    } else {
        const int* p = (const int*)ei;
        return p[(size_t)which * EE + e];
    }
}

// ---------------- CSR build ----------------
__global__ void csr_clear() {
    int i = blockIdx.x * blockDim.x + threadIdx.x;
    if (i < NN) { g_cnt[i] = 0; g_cursor[i] = 0; }
}

__global__ void csr_hist(const void* __restrict__ ei) {
    int e = blockIdx.x * blockDim.x + threadIdx.x;
    if (e < EE) atomicAdd(&g_cnt[load_idx(ei, 1, e)], 1);
}

__global__ void __launch_bounds__(1024) csr_scan1() {
    int i = blockIdx.x * 1024 + threadIdx.x;
    int v = (i < NN) ? g_cnt[i] : 0;
    int lane = threadIdx.x & 31, wid = threadIdx.x >> 5;
    int x = v;
#pragma unroll
    for (int off = 1; off < 32; off <<= 1) {
        int t = __shfl_up_sync(0xffffffffu, x, off);
        if (lane >= off) x += t;
    }
    __shared__ int wsum[32];
    if (lane == 31) wsum[wid] = x;
    __syncthreads();
    if (wid == 0) {
        int w = wsum[lane];
#pragma unroll
        for (int off = 1; off < 32; off <<= 1) {
            int t = __shfl_up_sync(0xffffffffu, w, off);
            if (lane >= off) w += t;
        }
        wsum[lane] = w;
    }
    __syncthreads();
    int base = wid ? wsum[wid - 1] : 0;
    if (i < NN) g_rowptr[i] = base + x - v;
    if (threadIdx.x == 0) g_bsum[blockIdx.x] = wsum[31];
}

__global__ void csr_scan2() {
    if (threadIdx.x == 0 && blockIdx.x == 0) {
        int run = 0;
        for (int b = 0; b < SCAN_BLOCKS; b++) { g_boff[b] = run; run += g_bsum[b]; }
        g_rowptr[NN] = run;
    }
}

__global__ void __launch_bounds__(1024) csr_scan3() {
    int i = blockIdx.x * 1024 + threadIdx.x;
    if (i < NN) g_rowptr[i] += g_boff[blockIdx.x];
}

__global__ void csr_fill(const void* __restrict__ ei) {
    int e = blockIdx.x * blockDim.x + threadIdx.x;
    if (e >= EE) return;
    int d = load_idx(ei, 1, e);
    int pos = atomicAdd(&g_cursor[d], 1);
    g_eidx[g_rowptr[d] + pos] = load_idx(ei, 0, e);
}

// ---------------- TF32 helpers ----------------
__device__ __forceinline__ uint32_t f2tf32(float x) {
    uint32_t r;
    asm("cvt.rna.tf32.f32 %0, %1;" : "=r"(r) : "f"(x));
    return r;
}
__device__ __forceinline__ void split_tf32(float v, uint32_t& hi, uint32_t& lo) {
    hi = f2tf32(v);
    lo = f2tf32(v - __uint_as_float(hi));
}
__device__ __forceinline__ void mma8(float* d, const uint32_t* a, const uint32_t* b) {
    asm volatile(
        "mma.sync.aligned.m16n8k8.row.col.f32.tf32.tf32.f32 "
        "{%0,%1,%2,%3}, {%4,%5,%6,%7}, {%8,%9}, {%0,%1,%2,%3};"
        : "+f"(d[0]), "+f"(d[1]), "+f"(d[2]), "+f"(d[3])
        : "r"(a[0]), "r"(a[1]), "r"(a[2]), "r"(a[3]), "r"(b[0]), "r"(b[1]));
}

// ---------------- merged TF32 GEMM pair: g_y = A@Bl, g_z = A@Br (+bias) -----
// BM=128, BN=64, BK=32, 256 threads = 8 warps (4 m x 2 n), warp tile 32x32 x2.
// 3xTF32 (hi*hi + hi*lo + lo*hi), in-loop splits (R11-proven), PLUS register
// prefetch of the next k-tile so global latency overlaps with MMA compute.
template <int NC, int A_FROM_H>
__global__ void __launch_bounds__(256) sgemm_pair_tc(const float* __restrict__ Aparam,
                                                     const float* __restrict__ Bl,
                                                     const float* __restrict__ Br,
                                                     const float* __restrict__ bias,
                                                     int M) {
    const float* A = A_FROM_H ? g_h : Aparam;
    const int K = 128;

    __shared__ float As[32][132];    // k-major, padded
    __shared__ float Bsl[32][68];
    __shared__ float Bsr[32][68];

    int tid = threadIdx.x;
    int wid = tid >> 5;
    int lane = tid & 31;
    int warp_m = wid & 3;            // 0..3 -> 32-row slice
    int warp_n = wid >> 2;           // 0..1 -> 32-col slice
    int r = lane >> 2;               // groupID 0..7
    int c = lane & 3;                // threadID_in_group 0..3

    int row0 = blockIdx.y * 128;
    int col0 = blockIdx.x * 64;

    float accl[2][4][4] = {};        // [mtile][ntile][frag]
    float accr[2][4][4] = {};

    // per-thread fixed load coordinates
    int a_r[4], a_c[4];
#pragma unroll
    for (int i = 0; i < 4; i++) { int f = tid + i * 256; a_r[i] = f >> 3; a_c[i] = f & 7; }
    int b_r[2], b_c[2];
#pragma unroll
    for (int i = 0; i < 2; i++) { int f = tid + i * 256; b_r[i] = f >> 4; b_c[i] = f & 15; }

    float4 pa[4], pbl[2], pbr[2];

    // ---- prologue: load tile k0=0 into regs ----
#pragma unroll
    for (int i = 0; i < 4; i++) {
        pa[i] = make_float4(0.f, 0.f, 0.f, 0.f);
        if (row0 + a_r[i] < M)
            pa[i] = *(const float4*)(A + (size_t)(row0 + a_r[i]) * K + a_c[i] * 4);
    }
#pragma unroll
    for (int i = 0; i < 2; i++) {
        pbl[i] = *(const float4*)(Bl + (size_t)b_r[i] * NC + col0 + b_c[i] * 4);
        pbr[i] = *(const float4*)(Br + (size_t)b_r[i] * NC + col0 + b_c[i] * 4);
    }
    // store to smem
#pragma unroll
    for (int i = 0; i < 4; i++) {
        As[a_c[i] * 4 + 0][a_r[i]] = pa[i].x;
        As[a_c[i] * 4 + 1][a_r[i]] = pa[i].y;
        As[a_c[i] * 4 + 2][a_r[i]] = pa[i].z;
        As[a_c[i] * 4 + 3][a_r[i]] = pa[i].w;
    }
#pragma unroll
    for (int i = 0; i < 2; i++) {
        *(float4*)&Bsl[b_r[i]][b_c[i] * 4] = pbl[i];
        *(float4*)&Bsr[b_r[i]][b_c[i] * 4] = pbr[i];
    }
    __syncthreads();

    for (int k0 = 0; k0 < K; k0 += 32) {
        // ---- prefetch next tile into registers (overlaps with MMAs below) ----
        if (k0 + 32 < K) {
            int kn = k0 + 32;
#pragma unroll
            for (int i = 0; i < 4; i++) {
                pa[i] = make_float4(0.f, 0.f, 0.f, 0.f);
                if (row0 + a_r[i] < M)
                    pa[i] = *(const float4*)(A + (size_t)(row0 + a_r[i]) * K + kn + a_c[i] * 4);
            }
#pragma unroll
            for (int i = 0; i < 2; i++) {
                pbl[i] = *(const float4*)(Bl + (size_t)(kn + b_r[i]) * NC + col0 + b_c[i] * 4);
                pbr[i] = *(const float4*)(Br + (size_t)(kn + b_r[i]) * NC + col0 + b_c[i] * 4);
            }
        }

        // ---- compute current tile (R11-identical) ----
#pragma unroll
        for (int kk = 0; kk < 32; kk += 8) {
            uint32_t ahi[2][4], alo[2][4];
#pragma unroll
            for (int mt = 0; mt < 2; mt++) {
                int m0 = warp_m * 32 + mt * 16;
                float a0 = As[kk + c][m0 + r];
                float a1 = As[kk + c][m0 + r + 8];
                float a2 = As[kk + c + 4][m0 + r];
                float a3 = As[kk + c + 4][m0 + r + 8];
                split_tf32(a0, ahi[mt][0], alo[mt][0]);
                split_tf32(a1, ahi[mt][1], alo[mt][1]);
                split_tf32(a2, ahi[mt][2], alo[mt][2]);
                split_tf32(a3, ahi[mt][3], alo[mt][3]);
            }
            uint32_t bhl[4][2], bll[4][2], bhr[4][2], blr[4][2];
#pragma unroll
            for (int nt = 0; nt < 4; nt++) {
                int n0 = warp_n * 32 + nt * 8 + r;
                float l0 = Bsl[kk + c][n0];
                float l1 = Bsl[kk + c + 4][n0];
                float r0 = Bsr[kk + c][n0];
                float r1 = Bsr[kk + c + 4][n0];
                split_tf32(l0, bhl[nt][0], bll[nt][0]);
                split_tf32(l1, bhl[nt][1], bll[nt][1]);
                split_tf32(r0, bhr[nt][0], blr[nt][0]);
                split_tf32(r1, bhr[nt][1], blr[nt][1]);
            }
#pragma unroll
            for (int mt = 0; mt < 2; mt++) {
#pragma unroll
                for (int nt = 0; nt < 4; nt++) {
                    mma8(accl[mt][nt], ahi[mt], bhl[nt]);
                    mma8(accl[mt][nt], ahi[mt], bll[nt]);
                    mma8(accl[mt][nt], alo[mt], bhl[nt]);
                    mma8(accr[mt][nt], ahi[mt], bhr[nt]);
                    mma8(accr[mt][nt], ahi[mt], blr[nt]);
                    mma8(accr[mt][nt], alo[mt], bhr[nt]);
                }
            }
        }
        __syncthreads();

        // ---- commit prefetched tile to smem ----
        if (k0 + 32 < K) {
#pragma unroll
            for (int i = 0; i < 4; i++) {
                As[a_c[i] * 4 + 0][a_r[i]] = pa[i].x;
                As[a_c[i] * 4 + 1][a_r[i]] = pa[i].y;
                As[a_c[i] * 4 + 2][a_r[i]] = pa[i].z;
                As[a_c[i] * 4 + 3][a_r[i]] = pa[i].w;
            }
#pragma unroll
            for (int i = 0; i < 2; i++) {
                *(float4*)&Bsl[b_r[i]][b_c[i] * 4] = pbl[i];
                *(float4*)&Bsr[b_r[i]][b_c[i] * 4] = pbr[i];
            }
            __syncthreads();
        }
    }

    // ---- epilogue ----
#pragma unroll
    for (int mt = 0; mt < 2; mt++) {
#pragma unroll
        for (int nt = 0; nt < 4; nt++) {
            int row = row0 + warp_m * 32 + mt * 16 + r;
            int col = col0 + warp_n * 32 + nt * 8 + 2 * c;
            float2 bb = *(const float2*)(bias + col);
            if (row < M) {
                *(float2*)(g_y + (size_t)row * NC + col) =
                    make_float2(accl[mt][nt][0], accl[mt][nt][1]);
                *(float2*)(g_z + (size_t)row * NC + col) =
                    make_float2(accr[mt][nt][0] + bb.x, accr[mt][nt][1] + bb.y);
            }
            if (row + 8 < M) {
                *(float2*)(g_y + (size_t)(row + 8) * NC + col) =
                    make_float2(accl[mt][nt][2], accl[mt][nt][3]);
                *(float2*)(g_z + (size_t)(row + 8) * NC + col) =
                    make_float2(accr[mt][nt][2] + bb.x, accr[mt][nt][3] + bb.y);
            }
        }
    }
}

// ---------------- fused gather + combine: warp per destination node ---------
template <bool RELU, bool TO_H>
__global__ void __launch_bounds__(256) gather128(float* __restrict__ outparam) {
    int w = (blockIdx.x * blockDim.x + threadIdx.x) >> 5;
    if (w >= NN) return;
    int lane = threadIdx.x & 31;
    int beg = g_rowptr[w], end = g_rowptr[w + 1];

    float4 acc = make_float4(0.f, 0.f, 0.f, 0.f);
    int j = beg;
    for (; j + 2 <= end; j += 2) {
        int s0 = g_eidx[j];
        int s1 = g_eidx[j + 1];
        float4 a = *(const float4*)(g_y + (size_t)s0 * 128 + lane * 4);
        float4 b = *(const float4*)(g_y + (size_t)s1 * 128 + lane * 4);
        acc.x += a.x + b.x; acc.y += a.y + b.y;
        acc.z += a.z + b.z; acc.w += a.w + b.w;
    }
    if (j < end) {
        int s0 = g_eidx[j];
        float4 a = *(const float4*)(g_y + (size_t)s0 * 128 + lane * 4);
        acc.x += a.x; acc.y += a.y; acc.z += a.z; acc.w += a.w;
    }

    float dv = 1.0f / fmaxf((float)(end - beg), 1.0f);
    float4 zz = *(const float4*)(g_z + (size_t)w * 128 + lane * 4);
    float4 o;
    o.x = acc.x * dv + zz.x;
    o.y = acc.y * dv + zz.y;
    o.z = acc.z * dv + zz.z;
    o.w = acc.w * dv + zz.w;
    if (RELU) {
        o.x = fmaxf(o.x, 0.f); o.y = fmaxf(o.y, 0.f);
        o.z = fmaxf(o.z, 0.f); o.w = fmaxf(o.w, 0.f);
    }
    float* out = TO_H ? g_h : outparam;
    *(float4*)(out + (size_t)w * 128 + lane * 4) = o;
}

template <bool RELU, bool TO_H>
__global__ void __launch_bounds__(256) gather64(float* __restrict__ outparam) {
    int w = (blockIdx.x * blockDim.x + threadIdx.x) >> 5;
    if (w >= NN) return;
    int lane = threadIdx.x & 31;
    int beg = g_rowptr[w], end = g_rowptr[w + 1];

    float2 acc = make_float2(0.f, 0.f);
    int j = beg;
    for (; j + 2 <= end; j += 2) {
        int s0 = g_eidx[j];
        int s1 = g_eidx[j + 1];
        float2 a = *(const float2*)(g_y + (size_t)s0 * 64 + lane * 2);
        float2 b = *(const float2*)(g_y + (size_t)s1 * 64 + lane * 2);
        acc.x += a.x + b.x; acc.y += a.y + b.y;
    }
    if (j < end) {
        int s0 = g_eidx[j];
        float2 a = *(const float2*)(g_y + (size_t)s0 * 64 + lane * 2);
        acc.x += a.x; acc.y += a.y;
    }

    float dv = 1.0f / fmaxf((float)(end - beg), 1.0f);
    float2 zz = *(const float2*)(g_z + (size_t)w * 64 + lane * 2);
    float2 o;
    o.x = acc.x * dv + zz.x;
    o.y = acc.y * dv + zz.y;
    if (RELU) { o.x = fmaxf(o.x, 0.f); o.y = fmaxf(o.y, 0.f); }
    float* out = TO_H ? g_h : outparam;
    *(float2*)(out + (size_t)w * 64 + lane * 2) = o;
}

// ---------------- launch ----------------
extern "C" void kernel_launch(void* const* d_in, const int* in_sizes, int n_in,
                              void* d_out, int out_size) {
    const float* x = (const float*)d_in[0];
    const void* ei = d_in[1];
    const float* Wl0 = (const float*)d_in[2];
    const float* b0  = (const float*)d_in[3];
    const float* Wr0 = (const float*)d_in[4];
    const float* Wl1 = (const float*)d_in[5];
    const float* b1  = (const float*)d_in[6];
    const float* Wr1 = (const float*)d_in[7];
    const float* Wl2 = (const float*)d_in[8];
    const float* b2  = (const float*)d_in[9];
    const float* Wr2 = (const float*)d_in[10];
    float* out = (float*)d_out;

    // ---- CSR build ----
    detect_dtype<<<1, 32>>>(ei);
    csr_clear<<<(NN + 255) / 256, 256>>>();
    csr_hist<<<(EE + 255) / 256, 256>>>(ei);
    csr_scan1<<<SCAN_BLOCKS, 1024>>>();
    csr_scan2<<<1, 32>>>();
    csr_scan3<<<SCAN_BLOCKS, 1024>>>();
    csr_fill<<<(EE + 255) / 256, 256>>>(ei);

    dim3 g128(2, (NN + 127) / 128);
    dim3 g64(1, (NN + 127) / 128);
    const int gather_blocks = (NN * 32 + 255) / 256;

    // ---- layer 0: input = x ----
    sgemm_pair_tc<128, 0><<<g128, 256>>>(x, Wl0, Wr0, b0, NN);
    gather128<true, true><<<gather_blocks, 256>>>(nullptr);

    // ---- layer 1: input = g_h ----
    sgemm_pair_tc<128, 1><<<g128, 256>>>(nullptr, Wl1, Wr1, b1, NN);
    gather128<true, true><<<gather_blocks, 256>>>(nullptr);

    // ---- layer 2: input = g_h, dout = 64 ----
    sgemm_pair_tc<64, 1><<<g64, 256>>>(nullptr, Wl2, Wr2, b2, NN);
    gather64<false, false><<<gather_blocks, 256>>>(out);
}

// round 16
// speedup vs baseline: 1.8516x; 1.1345x over previous
#include <cuda_runtime.h>
#include <cstdint>

#define NN 50000
#define EE 800000
#define SCAN_BLOCKS ((NN + 1023) / 1024)   // 49

// ---------------- scratch (device globals, referenced directly) -------------
__device__ float g_y[NN * 128];      // A @ Wl  (per layer)
__device__ float g_z[NN * 128];      // A @ Wr + b
__device__ float g_h[NN * 128];      // layer activation
__device__ int   g_rowptr[NN + 1];   // CSR row pointers (by dst)
__device__ int   g_cnt[NN];          // in-degree histogram
__device__ int   g_cursor[NN];       // fill cursors
__device__ int   g_eidx[EE];         // src node id per CSR slot
__device__ int   g_is64;             // edge_index dtype flag
__device__ int   g_bsum[SCAN_BLOCKS];
__device__ int   g_boff[SCAN_BLOCKS];

// ---------------- edge_index dtype detection --------------------------------
__global__ void detect_dtype(const void* __restrict__ ei) {
    if (threadIdx.x != 0 || blockIdx.x != 0) return;
    const long long* p = (const long long*)ei;
    int ok64 = 1;
    for (int i = 0; i < 64; i++) {
        long long v = p[i];
        if (v < 0 || v >= NN) { ok64 = 0; break; }
    }
    g_is64 = ok64;
}

__device__ __forceinline__ int load_idx(const void* __restrict__ ei, int which, int e) {
    if (g_is64) {
        const long long* p = (const long long*)ei;
        return (int)p[(size_t)which * EE + e];
    } else {
        const int* p = (const int*)ei;
        return p[(size_t)which * EE + e];
    }
}

// ---------------- CSR build ----------------
__global__ void csr_clear() {
    int i = blockIdx.x * blockDim.x + threadIdx.x;
    if (i < NN) { g_cnt[i] = 0; g_cursor[i] = 0; }
}

__global__ void csr_hist(const void* __restrict__ ei) {
    int e = blockIdx.x * blockDim.x + threadIdx.x;
    if (e < EE) atomicAdd(&g_cnt[load_idx(ei, 1, e)], 1);
}

__global__ void __launch_bounds__(1024) csr_scan1() {
    int i = blockIdx.x * 1024 + threadIdx.x;
    int v = (i < NN) ? g_cnt[i] : 0;
    int lane = threadIdx.x & 31, wid = threadIdx.x >> 5;
    int x = v;
#pragma unroll
    for (int off = 1; off < 32; off <<= 1) {
        int t = __shfl_up_sync(0xffffffffu, x, off);
        if (lane >= off) x += t;
    }
    __shared__ int wsum[32];
    if (lane == 31) wsum[wid] = x;
    __syncthreads();
    if (wid == 0) {
        int w = wsum[lane];
#pragma unroll
        for (int off = 1; off < 32; off <<= 1) {
            int t = __shfl_up_sync(0xffffffffu, w, off);
            if (lane >= off) w += t;
        }
        wsum[lane] = w;
    }
    __syncthreads();
    int base = wid ? wsum[wid - 1] : 0;
    if (i < NN) g_rowptr[i] = base + x - v;
    if (threadIdx.x == 0) g_bsum[blockIdx.x] = wsum[31];
}

__global__ void csr_scan2() {
    if (threadIdx.x == 0 && blockIdx.x == 0) {
        int run = 0;
        for (int b = 0; b < SCAN_BLOCKS; b++) { g_boff[b] = run; run += g_bsum[b]; }
        g_rowptr[NN] = run;
    }
}

__global__ void __launch_bounds__(1024) csr_scan3() {
    int i = blockIdx.x * 1024 + threadIdx.x;
    if (i < NN) g_rowptr[i] += g_boff[blockIdx.x];
}

__global__ void csr_fill(const void* __restrict__ ei) {
    int e = blockIdx.x * blockDim.x + threadIdx.x;
    if (e >= EE) return;
    int d = load_idx(ei, 1, e);
    int pos = atomicAdd(&g_cursor[d], 1);
    g_eidx[g_rowptr[d] + pos] = load_idx(ei, 0, e);
}

// ---------------- TF32 helpers ----------------
__device__ __forceinline__ uint32_t f2tf32(float x) {
    uint32_t r;
    asm("cvt.rna.tf32.f32 %0, %1;" : "=r"(r) : "f"(x));
    return r;
}
__device__ __forceinline__ void split_tf32(float v, uint32_t& hi, uint32_t& lo) {
    hi = f2tf32(v);
    lo = f2tf32(v - __uint_as_float(hi));
}
__device__ __forceinline__ void mma8(float* d, const uint32_t* a, const uint32_t* b) {
    asm volatile(
        "mma.sync.aligned.m16n8k8.row.col.f32.tf32.tf32.f32 "
        "{%0,%1,%2,%3}, {%4,%5,%6,%7}, {%8,%9}, {%0,%1,%2,%3};"
        : "+f"(d[0]), "+f"(d[1]), "+f"(d[2]), "+f"(d[3])
        : "r"(a[0]), "r"(a[1]), "r"(a[2]), "r"(a[3]), "r"(b[0]), "r"(b[1]));
}

// ---------------- merged TF32 GEMM pair: g_y = A@Bl, g_z = A@Br (+bias) -----
// BM=128, BN=64, BK=32, 256 threads = 8 warps (4 m x 2 n), warp tile 32x32 x2.
// 3xTF32 with in-loop splits — R11 configuration (measured best: 286.8us).
template <int NC, int A_FROM_H>
__global__ void __launch_bounds__(256) sgemm_pair_tc(const float* __restrict__ Aparam,
                                                     const float* __restrict__ Bl,
                                                     const float* __restrict__ Br,
                                                     const float* __restrict__ bias,
                                                     int M) {
    const float* A = A_FROM_H ? g_h : Aparam;
    const int K = 128;

    __shared__ float As[32][132];    // k-major, stride 132 (frag loads CF)
    __shared__ float Bsl[32][68];    // k-major, stride 68  (frag loads CF)
    __shared__ float Bsr[32][68];

    int tid = threadIdx.x;
    int wid = tid >> 5;
    int lane = tid & 31;
    int warp_m = wid & 3;            // 0..3 -> 32-row slice
    int warp_n = wid >> 2;           // 0..1 -> 32-col slice
    int r = lane >> 2;               // groupID 0..7
    int c = lane & 3;                // threadID_in_group 0..3

    int row0 = blockIdx.y * 128;
    int col0 = blockIdx.x * 64;

    float accl[2][4][4] = {};        // [mtile][ntile][frag]
    float accr[2][4][4] = {};

    for (int k0 = 0; k0 < K; k0 += 32) {
        // ---- fill As (128x32, transposed to k-major) ----
#pragma unroll
        for (int i = 0; i < 4; i++) {
            int f = tid + i * 256;               // 0..1023 float4 ids
            int ar = f >> 3, ac = f & 7;
            float4 v = make_float4(0.f, 0.f, 0.f, 0.f);
            if (row0 + ar < M)
                v = *(const float4*)(A + (size_t)(row0 + ar) * K + k0 + ac * 4);
            As[ac * 4 + 0][ar] = v.x;
            As[ac * 4 + 1][ar] = v.y;
            As[ac * 4 + 2][ar] = v.z;
            As[ac * 4 + 3][ar] = v.w;
        }
        // ---- fill Bsl/Bsr (each 32x64, natural k-major) ----
#pragma unroll
        for (int i = 0; i < 2; i++) {
            int f = tid + i * 256;               // 0..511
            int br = f >> 4, bc = f & 15;
            float4 wl = *(const float4*)(Bl + (size_t)(k0 + br) * NC + col0 + bc * 4);
            float4 wr = *(const float4*)(Br + (size_t)(k0 + br) * NC + col0 + bc * 4);
            *(float4*)&Bsl[br][bc * 4] = wl;
            *(float4*)&Bsr[br][bc * 4] = wr;
        }
        __syncthreads();

#pragma unroll
        for (int kk = 0; kk < 32; kk += 8) {
            // A fragments (2 m-tiles), split hi/lo
            uint32_t ahi[2][4], alo[2][4];
#pragma unroll
            for (int mt = 0; mt < 2; mt++) {
                int m0 = warp_m * 32 + mt * 16;
                float a0 = As[kk + c][m0 + r];
                float a1 = As[kk + c][m0 + r + 8];
                float a2 = As[kk + c + 4][m0 + r];
                float a3 = As[kk + c + 4][m0 + r + 8];
                split_tf32(a0, ahi[mt][0], alo[mt][0]);
                split_tf32(a1, ahi[mt][1], alo[mt][1]);
                split_tf32(a2, ahi[mt][2], alo[mt][2]);
                split_tf32(a3, ahi[mt][3], alo[mt][3]);
            }
            // B fragments (4 n-tiles per matrix), split hi/lo
            uint32_t bhl[4][2], bll[4][2], bhr[4][2], blr[4][2];
#pragma unroll
            for (int nt = 0; nt < 4; nt++) {
                int n0 = warp_n * 32 + nt * 8 + r;
                float l0 = Bsl[kk + c][n0];
                float l1 = Bsl[kk + c + 4][n0];
                float r0 = Bsr[kk + c][n0];
                float r1 = Bsr[kk + c + 4][n0];
                split_tf32(l0, bhl[nt][0], bll[nt][0]);
                split_tf32(l1, bhl[nt][1], bll[nt][1]);
                split_tf32(r0, bhr[nt][0], blr[nt][0]);
                split_tf32(r1, bhr[nt][1], blr[nt][1]);
            }
            // 3xTF32 MMAs
#pragma unroll
            for (int mt = 0; mt < 2; mt++) {
#pragma unroll
                for (int nt = 0; nt < 4; nt++) {
                    mma8(accl[mt][nt], ahi[mt], bhl[nt]);
                    mma8(accl[mt][nt], ahi[mt], bll[nt]);
                    mma8(accl[mt][nt], alo[mt], bhl[nt]);
                    mma8(accr[mt][nt], ahi[mt], bhr[nt]);
                    mma8(accr[mt][nt], ahi[mt], blr[nt]);
                    mma8(accr[mt][nt], alo[mt], bhr[nt]);
                }
            }
        }
        __syncthreads();
    }

    // ---- epilogue ----
#pragma unroll
    for (int mt = 0; mt < 2; mt++) {
#pragma unroll
        for (int nt = 0; nt < 4; nt++) {
            int row = row0 + warp_m * 32 + mt * 16 + r;
            int col = col0 + warp_n * 32 + nt * 8 + 2 * c;
            float2 bb = *(const float2*)(bias + col);
            if (row < M) {
                *(float2*)(g_y + (size_t)row * NC + col) =
                    make_float2(accl[mt][nt][0], accl[mt][nt][1]);
                *(float2*)(g_z + (size_t)row * NC + col) =
                    make_float2(accr[mt][nt][0] + bb.x, accr[mt][nt][1] + bb.y);
            }
            if (row + 8 < M) {
                *(float2*)(g_y + (size_t)(row + 8) * NC + col) =
                    make_float2(accl[mt][nt][2], accl[mt][nt][3]);
                *(float2*)(g_z + (size_t)(row + 8) * NC + col) =
                    make_float2(accr[mt][nt][2] + bb.x, accr[mt][nt][3] + bb.y);
            }
        }
    }
}

// ---------------- fused gather + combine: warp per destination node ---------
template <bool RELU, bool TO_H>
__global__ void __launch_bounds__(256) gather128(float* __restrict__ outparam) {
    int w = (blockIdx.x * blockDim.x + threadIdx.x) >> 5;
    if (w >= NN) return;
    int lane = threadIdx.x & 31;
    int beg = g_rowptr[w], end = g_rowptr[w + 1];

    float4 acc = make_float4(0.f, 0.f, 0.f, 0.f);
    int j = beg;
    for (; j + 2 <= end; j += 2) {
        int s0 = g_eidx[j];
        int s1 = g_eidx[j + 1];
        float4 a = *(const float4*)(g_y + (size_t)s0 * 128 + lane * 4);
        float4 b = *(const float4*)(g_y + (size_t)s1 * 128 + lane * 4);
        acc.x += a.x + b.x; acc.y += a.y + b.y;
        acc.z += a.z + b.z; acc.w += a.w + b.w;
    }
    if (j < end) {
        int s0 = g_eidx[j];
        float4 a = *(const float4*)(g_y + (size_t)s0 * 128 + lane * 4);
        acc.x += a.x; acc.y += a.y; acc.z += a.z; acc.w += a.w;
    }

    float dv = 1.0f / fmaxf((float)(end - beg), 1.0f);
    float4 zz = *(const float4*)(g_z + (size_t)w * 128 + lane * 4);
    float4 o;
    o.x = acc.x * dv + zz.x;
    o.y = acc.y * dv + zz.y;
    o.z = acc.z * dv + zz.z;
    o.w = acc.w * dv + zz.w;
    if (RELU) {
        o.x = fmaxf(o.x, 0.f); o.y = fmaxf(o.y, 0.f);
        o.z = fmaxf(o.z, 0.f); o.w = fmaxf(o.w, 0.f);
    }
    float* out = TO_H ? g_h : outparam;
    *(float4*)(out + (size_t)w * 128 + lane * 4) = o;
}

template <bool RELU, bool TO_H>
__global__ void __launch_bounds__(256) gather64(float* __restrict__ outparam) {
    int w = (blockIdx.x * blockDim.x + threadIdx.x) >> 5;
    if (w >= NN) return;
    int lane = threadIdx.x & 31;
    int beg = g_rowptr[w], end = g_rowptr[w + 1];

    float2 acc = make_float2(0.f, 0.f);
    int j = beg;
    for (; j + 2 <= end; j += 2) {
        int s0 = g_eidx[j];
        int s1 = g_eidx[j + 1];
        float2 a = *(const float2*)(g_y + (size_t)s0 * 64 + lane * 2);
        float2 b = *(const float2*)(g_y + (size_t)s1 * 64 + lane * 2);
        acc.x += a.x + b.x; acc.y += a.y + b.y;
    }
    if (j < end) {
        int s0 = g_eidx[j];
        float2 a = *(const float2*)(g_y + (size_t)s0 * 64 + lane * 2);
        acc.x += a.x; acc.y += a.y;
    }

    float dv = 1.0f / fmaxf((float)(end - beg), 1.0f);
    float2 zz = *(const float2*)(g_z + (size_t)w * 64 + lane * 2);
    float2 o;
    o.x = acc.x * dv + zz.x;
    o.y = acc.y * dv + zz.y;
    if (RELU) { o.x = fmaxf(o.x, 0.f); o.y = fmaxf(o.y, 0.f); }
    float* out = TO_H ? g_h : outparam;
    *(float2*)(out + (size_t)w * 64 + lane * 2) = o;
}

// ---------------- launch ----------------
extern "C" void kernel_launch(void* const* d_in, const int* in_sizes, int n_in,
                              void* d_out, int out_size) {
    const float* x = (const float*)d_in[0];
    const void* ei = d_in[1];
    const float* Wl0 = (const float*)d_in[2];
    const float* b0  = (const float*)d_in[3];
    const float* Wr0 = (const float*)d_in[4];
    const float* Wl1 = (const float*)d_in[5];
    const float* b1  = (const float*)d_in[6];
    const float* Wr1 = (const float*)d_in[7];
    const float* Wl2 = (const float*)d_in[8];
    const float* b2  = (const float*)d_in[9];
    const float* Wr2 = (const float*)d_in[10];
    float* out = (float*)d_out;

    // side stream + events: created once (host-side resources, no device mem)
    static cudaStream_t s_side = nullptr;
    static cudaEvent_t s_fork = nullptr, s_join = nullptr;
    if (!s_side) {
        cudaStreamCreateWithFlags(&s_side, cudaStreamNonBlocking);
        cudaEventCreateWithFlags(&s_fork, cudaEventDisableTiming);
        cudaEventCreateWithFlags(&s_join, cudaEventDisableTiming);
    }

    // ---- fork: CSR build on side stream, overlapped with layer-0 GEMM ----
    cudaEventRecord(s_fork, 0);
    cudaStreamWaitEvent(s_side, s_fork, 0);

    detect_dtype<<<1, 32, 0, s_side>>>(ei);
    csr_clear<<<(NN + 255) / 256, 256, 0, s_side>>>();
    csr_hist<<<(EE + 255) / 256, 256, 0, s_side>>>(ei);
    csr_scan1<<<SCAN_BLOCKS, 1024, 0, s_side>>>();
    csr_scan2<<<1, 32, 0, s_side>>>();
    csr_scan3<<<SCAN_BLOCKS, 1024, 0, s_side>>>();
    csr_fill<<<(EE + 255) / 256, 256, 0, s_side>>>(ei);
    cudaEventRecord(s_join, s_side);

    dim3 g128(2, (NN + 127) / 128);
    dim3 g64(1, (NN + 127) / 128);
    const int gather_blocks = (NN * 32 + 255) / 256;

    // ---- layer 0: input = x (GEMM runs concurrently with CSR build) ----
    sgemm_pair_tc<128, 0><<<g128, 256>>>(x, Wl0, Wr0, b0, NN);

    // join: gather needs CSR
    cudaStreamWaitEvent(0, s_join, 0);
    gather128<true, true><<<gather_blocks, 256>>>(nullptr);

    // ---- layer 1: input = g_h ----
    sgemm_pair_tc<128, 1><<<g128, 256>>>(nullptr, Wl1, Wr1, b1, NN);
    gather128<true, true><<<gather_blocks, 256>>>(nullptr);

    // ---- layer 2: input = g_h, dout = 64 ----
    sgemm_pair_tc<64, 1><<<g64, 256>>>(nullptr, Wl2, Wr2, b2, NN);
    gather64<false, false><<<gather_blocks, 256>>>(out);
}

// round 17
// speedup vs baseline: 1.9867x; 1.0730x over previous
#include <cuda_runtime.h>
#include <cuda_fp16.h>
#include <cstdint>

#define NN 50000
#define EE 800000
#define SCAN_BLOCKS ((NN + 1023) / 1024)   // 49

// ---------------- scratch (device globals, referenced directly) -------------
__device__ __half g_yh[NN * 128];    // A @ Wl  (per layer), fp16 — gather-only
__device__ float g_z[NN * 128];      // A @ Wr + b (fp32)
__device__ float g_h[NN * 128];      // layer activation (fp32)
__device__ int   g_rowptr[NN + 1];   // CSR row pointers (by dst)
__device__ int   g_cnt[NN];          // in-degree histogram
__device__ int   g_cursor[NN];       // fill cursors
__device__ int   g_eidx[EE];         // src node id per CSR slot
__device__ int   g_is64;             // edge_index dtype flag
__device__ int   g_bsum[SCAN_BLOCKS];
__device__ int   g_boff[SCAN_BLOCKS];

// ---------------- edge_index dtype detection --------------------------------
__global__ void detect_dtype(const void* __restrict__ ei) {
    if (threadIdx.x != 0 || blockIdx.x != 0) return;
    const long long* p = (const long long*)ei;
    int ok64 = 1;
    for (int i = 0; i < 64; i++) {
        long long v = p[i];
        if (v < 0 || v >= NN) { ok64 = 0; break; }
    }
    g_is64 = ok64;
}

__device__ __forceinline__ int load_idx(const void* __restrict__ ei, int which, int e) {
    if (g_is64) {
        const long long* p = (const long long*)ei;
        return (int)p[(size_t)which * EE + e];
    } else {
        const int* p = (const int*)ei;
        return p[(size_t)which * EE + e];
    }
}

// ---------------- CSR build ----------------
__global__ void csr_clear() {
    int i = blockIdx.x * blockDim.x + threadIdx.x;
    if (i < NN) { g_cnt[i] = 0; g_cursor[i] = 0; }
}

__global__ void csr_hist(const void* __restrict__ ei) {
    int e = blockIdx.x * blockDim.x + threadIdx.x;
    if (e < EE) atomicAdd(&g_cnt[load_idx(ei, 1, e)], 1);
}

__global__ void __launch_bounds__(1024) csr_scan1() {
    int i = blockIdx.x * 1024 + threadIdx.x;
    int v = (i < NN) ? g_cnt[i] : 0;
    int lane = threadIdx.x & 31, wid = threadIdx.x >> 5;
    int x = v;
#pragma unroll
    for (int off = 1; off < 32; off <<= 1) {
        int t = __shfl_up_sync(0xffffffffu, x, off);
        if (lane >= off) x += t;
    }
    __shared__ int wsum[32];
    if (lane == 31) wsum[wid] = x;
    __syncthreads();
    if (wid == 0) {
        int w = wsum[lane];
#pragma unroll
        for (int off = 1; off < 32; off <<= 1) {
            int t = __shfl_up_sync(0xffffffffu, w, off);
            if (lane >= off) w += t;
        }
        wsum[lane] = w;
    }
    __syncthreads();
    int base = wid ? wsum[wid - 1] : 0;
    if (i < NN) g_rowptr[i] = base + x - v;
    if (threadIdx.x == 0) g_bsum[blockIdx.x] = wsum[31];
}

__global__ void csr_scan2() {
    if (threadIdx.x == 0 && blockIdx.x == 0) {
        int run = 0;
        for (int b = 0; b < SCAN_BLOCKS; b++) { g_boff[b] = run; run += g_bsum[b]; }
        g_rowptr[NN] = run;
    }
}

__global__ void __launch_bounds__(1024) csr_scan3() {
    int i = blockIdx.x * 1024 + threadIdx.x;
    if (i < NN) g_rowptr[i] += g_boff[blockIdx.x];
}

__global__ void csr_fill(const void* __restrict__ ei) {
    int e = blockIdx.x * blockDim.x + threadIdx.x;
    if (e >= EE) return;
    int d = load_idx(ei, 1, e);
    int pos = atomicAdd(&g_cursor[d], 1);
    g_eidx[g_rowptr[d] + pos] = load_idx(ei, 0, e);
}

// ---------------- TF32 helpers ----------------
__device__ __forceinline__ uint32_t f2tf32(float x) {
    uint32_t r;
    asm("cvt.rna.tf32.f32 %0, %1;" : "=r"(r) : "f"(x));
    return r;
}
__device__ __forceinline__ void split_tf32(float v, uint32_t& hi, uint32_t& lo) {
    hi = f2tf32(v);
    lo = f2tf32(v - __uint_as_float(hi));
}
__device__ __forceinline__ void mma8(float* d, const uint32_t* a, const uint32_t* b) {
    asm volatile(
        "mma.sync.aligned.m16n8k8.row.col.f32.tf32.tf32.f32 "
        "{%0,%1,%2,%3}, {%4,%5,%6,%7}, {%8,%9}, {%0,%1,%2,%3};"
        : "+f"(d[0]), "+f"(d[1]), "+f"(d[2]), "+f"(d[3])
        : "r"(a[0]), "r"(a[1]), "r"(a[2]), "r"(a[3]), "r"(b[0]), "r"(b[1]));
}

// ---------------- merged TF32 GEMM pair: g_yh = A@Bl (fp16), g_z = A@Br (+bias)
// BM=128, BN=64, BK=32, 256 threads = 8 warps (4 m x 2 n), warp tile 32x32 x2.
// 3xTF32 with in-loop splits — R11 configuration (measured best).
template <int NC, int A_FROM_H>
__global__ void __launch_bounds__(256) sgemm_pair_tc(const float* __restrict__ Aparam,
                                                     const float* __restrict__ Bl,
                                                     const float* __restrict__ Br,
                                                     const float* __restrict__ bias,
                                                     int M) {
    const float* A = A_FROM_H ? g_h : Aparam;
    const int K = 128;

    __shared__ float As[32][132];    // k-major, stride 132 (frag loads CF)
    __shared__ float Bsl[32][68];    // k-major, stride 68  (frag loads CF)
    __shared__ float Bsr[32][68];

    int tid = threadIdx.x;
    int wid = tid >> 5;
    int lane = tid & 31;
    int warp_m = wid & 3;            // 0..3 -> 32-row slice
    int warp_n = wid >> 2;           // 0..1 -> 32-col slice
    int r = lane >> 2;               // groupID 0..7
    int c = lane & 3;                // threadID_in_group 0..3

    int row0 = blockIdx.y * 128;
    int col0 = blockIdx.x * 64;

    float accl[2][4][4] = {};        // [mtile][ntile][frag]
    float accr[2][4][4] = {};

    for (int k0 = 0; k0 < K; k0 += 32) {
        // ---- fill As (128x32, transposed to k-major) ----
#pragma unroll
        for (int i = 0; i < 4; i++) {
            int f = tid + i * 256;               // 0..1023 float4 ids
            int ar = f >> 3, ac = f & 7;
            float4 v = make_float4(0.f, 0.f, 0.f, 0.f);
            if (row0 + ar < M)
                v = *(const float4*)(A + (size_t)(row0 + ar) * K + k0 + ac * 4);
            As[ac * 4 + 0][ar] = v.x;
            As[ac * 4 + 1][ar] = v.y;
            As[ac * 4 + 2][ar] = v.z;
            As[ac * 4 + 3][ar] = v.w;
        }
        // ---- fill Bsl/Bsr (each 32x64, natural k-major) ----
#pragma unroll
        for (int i = 0; i < 2; i++) {
            int f = tid + i * 256;               // 0..511
            int br = f >> 4, bc = f & 15;
            float4 wl = *(const float4*)(Bl + (size_t)(k0 + br) * NC + col0 + bc * 4);
            float4 wr = *(const float4*)(Br + (size_t)(k0 + br) * NC + col0 + bc * 4);
            *(float4*)&Bsl[br][bc * 4] = wl;
            *(float4*)&Bsr[br][bc * 4] = wr;
        }
        __syncthreads();

#pragma unroll
        for (int kk = 0; kk < 32; kk += 8) {
            // A fragments (2 m-tiles), split hi/lo
            uint32_t ahi[2][4], alo[2][4];
#pragma unroll
            for (int mt = 0; mt < 2; mt++) {
                int m0 = warp_m * 32 + mt * 16;
                float a0 = As[kk + c][m0 + r];
                float a1 = As[kk + c][m0 + r + 8];
                float a2 = As[kk + c + 4][m0 + r];
                float a3 = As[kk + c + 4][m0 + r + 8];
                split_tf32(a0, ahi[mt][0], alo[mt][0]);
                split_tf32(a1, ahi[mt][1], alo[mt][1]);
                split_tf32(a2, ahi[mt][2], alo[mt][2]);
                split_tf32(a3, ahi[mt][3], alo[mt][3]);
            }
            // B fragments (4 n-tiles per matrix), split hi/lo
            uint32_t bhl[4][2], bll[4][2], bhr[4][2], blr[4][2];
#pragma unroll
            for (int nt = 0; nt < 4; nt++) {
                int n0 = warp_n * 32 + nt * 8 + r;
                float l0 = Bsl[kk + c][n0];
                float l1 = Bsl[kk + c + 4][n0];
                float r0 = Bsr[kk + c][n0];
                float r1 = Bsr[kk + c + 4][n0];
                split_tf32(l0, bhl[nt][0], bll[nt][0]);
                split_tf32(l1, bhl[nt][1], bll[nt][1]);
                split_tf32(r0, bhr[nt][0], blr[nt][0]);
                split_tf32(r1, bhr[nt][1], blr[nt][1]);
            }
            // 3xTF32 MMAs
#pragma unroll
            for (int mt = 0; mt < 2; mt++) {
#pragma unroll
                for (int nt = 0; nt < 4; nt++) {
                    mma8(accl[mt][nt], ahi[mt], bhl[nt]);
                    mma8(accl[mt][nt], ahi[mt], bll[nt]);
                    mma8(accl[mt][nt], alo[mt], bhl[nt]);
                    mma8(accr[mt][nt], ahi[mt], bhr[nt]);
                    mma8(accr[mt][nt], ahi[mt], blr[nt]);
                    mma8(accr[mt][nt], alo[mt], bhr[nt]);
                }
            }
        }
        __syncthreads();
    }

    // ---- epilogue: y -> fp16 (gather-only consumer), z -> fp32 ----
#pragma unroll
    for (int mt = 0; mt < 2; mt++) {
#pragma unroll
        for (int nt = 0; nt < 4; nt++) {
            int row = row0 + warp_m * 32 + mt * 16 + r;
            int col = col0 + warp_n * 32 + nt * 8 + 2 * c;
            float2 bb = *(const float2*)(bias + col);
            if (row < M) {
                *(__half2*)(g_yh + (size_t)row * NC + col) =
                    __floats2half2_rn(accl[mt][nt][0], accl[mt][nt][1]);
                *(float2*)(g_z + (size_t)row * NC + col) =
                    make_float2(accr[mt][nt][0] + bb.x, accr[mt][nt][1] + bb.y);
            }
            if (row + 8 < M) {
                *(__half2*)(g_yh + (size_t)(row + 8) * NC + col) =
                    __floats2half2_rn(accl[mt][nt][2], accl[mt][nt][3]);
                *(float2*)(g_z + (size_t)(row + 8) * NC + col) =
                    make_float2(accr[mt][nt][2] + bb.x, accr[mt][nt][3] + bb.y);
            }
        }
    }
}

// ---------------- fused gather + combine: warp per destination node ---------
// out[d] = act( mean_{s in N(d)} y[s]  +  z[d] ), y rows in fp16 (half L2 B/W)
template <bool RELU, bool TO_H>
__global__ void __launch_bounds__(256) gather128(float* __restrict__ outparam) {
    int w = (blockIdx.x * blockDim.x + threadIdx.x) >> 5;
    if (w >= NN) return;
    int lane = threadIdx.x & 31;
    int beg = g_rowptr[w], end = g_rowptr[w + 1];

    // lane covers 4 consecutive channels: cols lane*4 .. lane*4+3
    float4 acc = make_float4(0.f, 0.f, 0.f, 0.f);
    for (int j = beg; j < end; j++) {
        int s = g_eidx[j];                      // lane-uniform -> broadcast
        uint2 v = *(const uint2*)(g_yh + (size_t)s * 128 + lane * 4);   // 8B
        __half2 h0 = *reinterpret_cast<__half2*>(&v.x);
        __half2 h1 = *reinterpret_cast<__half2*>(&v.y);
        float2 f0 = __half22float2(h0);
        float2 f1 = __half22float2(h1);
        acc.x += f0.x; acc.y += f0.y; acc.z += f1.x; acc.w += f1.y;
    }

    float dv = 1.0f / fmaxf((float)(end - beg), 1.0f);
    float4 zz = *(const float4*)(g_z + (size_t)w * 128 + lane * 4);
    float4 o;
    o.x = acc.x * dv + zz.x;
    o.y = acc.y * dv + zz.y;
    o.z = acc.z * dv + zz.z;
    o.w = acc.w * dv + zz.w;
    if (RELU) {
        o.x = fmaxf(o.x, 0.f); o.y = fmaxf(o.y, 0.f);
        o.z = fmaxf(o.z, 0.f); o.w = fmaxf(o.w, 0.f);
    }
    float* out = TO_H ? g_h : outparam;
    *(float4*)(out + (size_t)w * 128 + lane * 4) = o;
}

template <bool RELU, bool TO_H>
__global__ void __launch_bounds__(256) gather64(float* __restrict__ outparam) {
    int w = (blockIdx.x * blockDim.x + threadIdx.x) >> 5;
    if (w >= NN) return;
    int lane = threadIdx.x & 31;
    int beg = g_rowptr[w], end = g_rowptr[w + 1];

    // lane covers 2 consecutive channels
    float2 acc = make_float2(0.f, 0.f);
    for (int j = beg; j < end; j++) {
        int s = g_eidx[j];
        __half2 h = *(const __half2*)(g_yh + (size_t)s * 64 + lane * 2);   // 4B
        float2 f = __half22float2(h);
        acc.x += f.x; acc.y += f.y;
    }

    float dv = 1.0f / fmaxf((float)(end - beg), 1.0f);
    float2 zz = *(const float2*)(g_z + (size_t)w * 64 + lane * 2);
    float2 o;
    o.x = acc.x * dv + zz.x;
    o.y = acc.y * dv + zz.y;
    if (RELU) { o.x = fmaxf(o.x, 0.f); o.y = fmaxf(o.y, 0.f); }
    float* out = TO_H ? g_h : outparam;
    *(float2*)(out + (size_t)w * 64 + lane * 2) = o;
}

// ---------------- launch ----------------
extern "C" void kernel_launch(void* const* d_in, const int* in_sizes, int n_in,
                              void* d_out, int out_size) {
    const float* x = (const float*)d_in[0];
    const void* ei = d_in[1];
    const float* Wl0 = (const float*)d_in[2];
    const float* b0  = (const float*)d_in[3];
    const float* Wr0 = (const float*)d_in[4];
    const float* Wl1 = (const float*)d_in[5];
    const float* b1  = (const float*)d_in[6];
    const float* Wr1 = (const float*)d_in[7];
    const float* Wl2 = (const float*)d_in[8];
    const float* b2  = (const float*)d_in[9];
    const float* Wr2 = (const float*)d_in[10];
    float* out = (float*)d_out;

    // side stream + events: created once (host-side resources, no device mem)
    static cudaStream_t s_side = nullptr;
    static cudaEvent_t s_fork = nullptr, s_join = nullptr;
    if (!s_side) {
        cudaStreamCreateWithFlags(&s_side, cudaStreamNonBlocking);
        cudaEventCreateWithFlags(&s_fork, cudaEventDisableTiming);
        cudaEventCreateWithFlags(&s_join, cudaEventDisableTiming);
    }

    // ---- fork: CSR build on side stream, overlapped with layer-0 GEMM ----
    cudaEventRecord(s_fork, 0);
    cudaStreamWaitEvent(s_side, s_fork, 0);

    detect_dtype<<<1, 32, 0, s_side>>>(ei);
    csr_clear<<<(NN + 255) / 256, 256, 0, s_side>>>();
    csr_hist<<<(EE + 255) / 256, 256, 0, s_side>>>(ei);
    csr_scan1<<<SCAN_BLOCKS, 1024, 0, s_side>>>();
    csr_scan2<<<1, 32, 0, s_side>>>();
    csr_scan3<<<SCAN_BLOCKS, 1024, 0, s_side>>>();
    csr_fill<<<(EE + 255) / 256, 256, 0, s_side>>>(ei);
    cudaEventRecord(s_join, s_side);

    dim3 g128(2, (NN + 127) / 128);
    dim3 g64(1, (NN + 127) / 128);
    const int gather_blocks = (NN * 32 + 255) / 256;

    // ---- layer 0: input = x (GEMM runs concurrently with CSR build) ----
    sgemm_pair_tc<128, 0><<<g128, 256>>>(x, Wl0, Wr0, b0, NN);

    // join: gather needs CSR
    cudaStreamWaitEvent(0, s_join, 0);
    gather128<true, true><<<gather_blocks, 256>>>(nullptr);

    // ---- layer 1: input = g_h ----
    sgemm_pair_tc<128, 1><<<g128, 256>>>(nullptr, Wl1, Wr1, b1, NN);
    gather128<true, true><<<gather_blocks, 256>>>(nullptr);

    // ---- layer 2: input = g_h, dout = 64 ----
    sgemm_pair_tc<64, 1><<<g64, 256>>>(nullptr, Wl2, Wr2, b2, NN);
    gather64<false, false><<<gather_blocks, 256>>>(out);
}